// round 1
// baseline (speedup 1.0000x reference)
#include <cuda_runtime.h>
#include <cstdint>

#define NB 200000
#define NC 20000
#define NT 2000
#define DD 128

// ---------------- scratch (device globals; no allocation allowed) ------------
__device__ float g_hs1[(size_t)NB * DD];   // x_building @ Ws1
__device__ float g_xwg[(size_t)NB * DD];   // x_building @ Wg
__device__ float g_aggB[(size_t)NB * DD];  // GCN accumulation
__device__ float g_hd1[(size_t)NC * DD];   // x_cable @ Wd1
__device__ float g_hs2[(size_t)NC * DD];   // h_cable @ Ws2
__device__ float g_num1[(size_t)NC * DD];  // GAT1 numerator
__device__ float g_hd2[(size_t)NT * DD];   // x_transformer @ Wd2
__device__ float g_num2[(size_t)NT * DD];  // GAT2 numerator
__device__ float g_es1[NB * 4];
__device__ float g_ed1[NC * 4];
__device__ float g_es2[NC * 4];
__device__ float g_ed2[NT * 4];
__device__ float g_m1[NC * 4];
__device__ float g_s1[NC * 4];
__device__ float g_m2[NT * 4];
__device__ float g_s2[NT * 4];
__device__ float g_e1[200000 * 4];  // GAT1 edge logits -> weights
__device__ float g_e2[20000 * 4];
__device__ float g_deg[NB];
__device__ float g_dinv[NB];

// ---------------- helpers ----------------------------------------------------
__device__ __forceinline__ unsigned long long f2ull(float x, float y) {
    unsigned long long r;
    asm("mov.b64 %0, {%1,%2};" : "=l"(r) : "f"(x), "f"(y));
    return r;
}
__device__ __forceinline__ float2 ull2f2(unsigned long long v) {
    float2 r;
    asm("mov.b64 {%0,%1}, %2;" : "=f"(r.x), "=f"(r.y) : "l"(v));
    return r;
}
#define FMA2(acc, a, b) asm("fma.rn.f32x2 %0, %1, %2, %0;" : "+l"(acc) : "l"(a), "l"(b))

__device__ __forceinline__ void redAddV4(float* p, float a, float b, float c, float d) {
    asm volatile("red.global.add.v4.f32 [%0], {%1,%2,%3,%4};"
                 :: "l"(p), "f"(a), "f"(b), "f"(c), "f"(d) : "memory");
}

__device__ __forceinline__ void atomicMaxFloat(float* addr, float v) {
    if (v >= 0.0f) atomicMax((int*)addr, __float_as_int(v));
    else atomicMin((unsigned int*)addr, (unsigned int)__float_as_int(v));
}

// ---------------- init: zero accumulators, set maxes to -inf ------------------
__global__ void init_kernel() {
    int idx = blockIdx.x * blockDim.x + threadIdx.x;
    int stride = gridDim.x * blockDim.x;
    float4 z = make_float4(0.f, 0.f, 0.f, 0.f);
    for (int i = idx; i < NB * DD / 4; i += stride) ((float4*)g_aggB)[i] = z;
    for (int i = idx; i < NC * DD / 4; i += stride) ((float4*)g_num1)[i] = z;
    for (int i = idx; i < NT * DD / 4; i += stride) ((float4*)g_num2)[i] = z;
    for (int i = idx; i < NB; i += stride) g_deg[i] = 0.f;
    for (int i = idx; i < NC * 4; i += stride) { g_s1[i] = 0.f; g_m1[i] = -1e30f; }
    for (int i = idx; i < NT * 4; i += stride) { g_s2[i] = 0.f; g_m2[i] = -1e30f; }
}

// ---------------- fp32 GEMM, W fully SMEM-resident, FFMA2 inner loop ----------
// O[row, col] = sum_k X[row,k] * W[k,col], K = 128 fixed, NCOLS = 128 or 256.
// 512 threads, 128-row tiles, thread micro-tile 4 rows x (NCOLS/64) float4 cols,
// accumulators held as f32x2 pairs.
template <int NCOLS>
__global__ void __launch_bounds__(512, 1)
gemm_kernel(const float* __restrict__ X, int M, int ntiles,
            const float* __restrict__ W0, const float* __restrict__ W1,
            float* __restrict__ O0, float* __restrict__ O1) {
    extern __shared__ float smem[];
    float* sW = smem;                 // 128 * NCOLS
    float* sX = smem + 128 * NCOLS;   // 128 rows * 132 (padded)
    const int tid = threadIdx.x;

    // Load W (and W1 side-by-side for the dual case)
    for (int i = tid; i < 128 * NCOLS / 4; i += 512) {
        int k = (i * 4) / NCOLS;
        int n = (i * 4) % NCOLS;
        const float* src = (n < 128) ? &W0[k * 128 + n] : &W1[k * 128 + (n - 128)];
        *(float4*)&sW[i * 4] = *(const float4*)src;
    }

    const int tx = tid & 15;
    const int ty = tid >> 4;
    constexpr int NCH = NCOLS / 64;

    for (int tile = blockIdx.x; tile < ntiles; tile += gridDim.x) {
        int row0 = tile * 128;
        __syncthreads();
        for (int i = tid; i < 128 * 32; i += 512) {
            int r = i >> 5;
            int c4 = (i & 31) * 4;
            float4 v = make_float4(0.f, 0.f, 0.f, 0.f);
            if (row0 + r < M) v = *(const float4*)&X[(size_t)(row0 + r) * 128 + c4];
            *(float4*)&sX[r * 132 + c4] = v;
        }
        __syncthreads();

        unsigned long long acc[4][NCH][2];
        #pragma unroll
        for (int i = 0; i < 4; i++)
            #pragma unroll
            for (int c = 0; c < NCH; c++) { acc[i][c][0] = 0ull; acc[i][c][1] = 0ull; }

        #pragma unroll 4
        for (int k = 0; k < 128; k++) {
            unsigned long long a2[4];
            #pragma unroll
            for (int i = 0; i < 4; i++) {
                float av = sX[(ty * 4 + i) * 132 + k];
                a2[i] = f2ull(av, av);
            }
            #pragma unroll
            for (int c = 0; c < NCH; c++) {
                ulonglong2 b = *(const ulonglong2*)&sW[k * NCOLS + c * 64 + tx * 4];
                #pragma unroll
                for (int i = 0; i < 4; i++) {
                    FMA2(acc[i][c][0], a2[i], b.x);
                    FMA2(acc[i][c][1], a2[i], b.y);
                }
            }
        }

        #pragma unroll
        for (int i = 0; i < 4; i++) {
            int row = row0 + ty * 4 + i;
            if (row >= M) continue;
            #pragma unroll
            for (int c = 0; c < NCH; c++) {
                int col = c * 64 + tx * 4;
                float2 lo = ull2f2(acc[i][c][0]);
                float2 hi = ull2f2(acc[i][c][1]);
                float4 v = make_float4(lo.x, lo.y, hi.x, hi.y);
                if (col < 128) *(float4*)&O0[(size_t)row * 128 + col] = v;
                else           *(float4*)&O1[(size_t)row * 128 + col - 128] = v;
            }
        }
    }
}

// ---------------- per-node attention dot: out[n,h] = sum_c h[n,h,c]*a[h,c] ----
__global__ void alpha_kernel(const float* __restrict__ h, const float* __restrict__ a,
                             float* __restrict__ out, int N) {
    int gt = blockIdx.x * blockDim.x + threadIdx.x;
    int n = gt >> 5;
    int lane = threadIdx.x & 31;
    if (n >= N) return;
    float4 hv = *(const float4*)&h[(size_t)n * 128 + lane * 4];
    float4 av = *(const float4*)&a[lane * 4];
    float p = hv.x * av.x + hv.y * av.y + hv.z * av.z + hv.w * av.w;
    p += __shfl_down_sync(0xffffffffu, p, 4, 8);
    p += __shfl_down_sync(0xffffffffu, p, 2, 8);
    p += __shfl_down_sync(0xffffffffu, p, 1, 8);
    if ((lane & 7) == 0) out[n * 4 + (lane >> 3)] = p;
}

// ---------------- GAT pass A: logits + segment max ---------------------------
__global__ void gat_logit_max(const float* __restrict__ es, const float* __restrict__ ed,
                              const int* __restrict__ src, const int* __restrict__ dst,
                              int E, float* __restrict__ elog, float* __restrict__ m) {
    int e = blockIdx.x * blockDim.x + threadIdx.x;
    if (e >= E) return;
    int s = src[e], d = dst[e];
    float4 a = *(const float4*)&es[s * 4];
    float4 b = *(const float4*)&ed[d * 4];
    float4 v;
    float t;
    t = a.x + b.x; v.x = t > 0.f ? t : 0.2f * t;
    t = a.y + b.y; v.y = t > 0.f ? t : 0.2f * t;
    t = a.z + b.z; v.z = t > 0.f ? t : 0.2f * t;
    t = a.w + b.w; v.w = t > 0.f ? t : 0.2f * t;
    *(float4*)&elog[e * 4] = v;
    atomicMaxFloat(&m[d * 4 + 0], v.x);
    atomicMaxFloat(&m[d * 4 + 1], v.y);
    atomicMaxFloat(&m[d * 4 + 2], v.z);
    atomicMaxFloat(&m[d * 4 + 3], v.w);
}

// ---------------- GAT pass B: exp, segment sum, weighted numerator -----------
// one warp per edge; lane l covers cols l*4..l*4+3 (head = l>>3)
__global__ void gat_accum(const float* __restrict__ elog, const float* __restrict__ m,
                          float* __restrict__ ssum, const float* __restrict__ hs,
                          const int* __restrict__ src, const int* __restrict__ dst,
                          float* __restrict__ num, int E) {
    int gt = blockIdx.x * blockDim.x + threadIdx.x;
    int e = gt >> 5;
    if (e >= E) return;
    int lane = threadIdx.x & 31;
    int s = src[e], d = dst[e];
    int h = lane >> 3;
    float w = __expf(elog[e * 4 + h] - m[d * 4 + h]);
    if ((lane & 7) == 0) atomicAdd(&ssum[d * 4 + h], w);
    float4 hv = *(const float4*)&hs[(size_t)s * 128 + lane * 4];
    redAddV4(&num[(size_t)d * 128 + lane * 4], w * hv.x, w * hv.y, w * hv.z, w * hv.w);
}

// ---------------- GAT finalize: out = x + 0.5*(num/(s+eps) + bias) -----------
__global__ void gat_finalize(const float* __restrict__ x, const float* __restrict__ num,
                             const float* __restrict__ ssum, const float* __restrict__ bias,
                             float* __restrict__ out, int N) {
    int gt = blockIdx.x * blockDim.x + threadIdx.x;
    int n = gt >> 5;
    int lane = threadIdx.x & 31;
    if (n >= N) return;
    int h = lane >> 3;
    float inv = 1.0f / (ssum[n * 4 + h] + 1e-16f);
    int c = lane * 4;
    float4 nv = *(const float4*)&num[(size_t)n * 128 + c];
    float4 xv = *(const float4*)&x[(size_t)n * 128 + c];
    float4 bv = *(const float4*)&bias[c];
    float4 o;
    o.x = xv.x + 0.5f * (nv.x * inv + bv.x);
    o.y = xv.y + 0.5f * (nv.y * inv + bv.y);
    o.z = xv.z + 0.5f * (nv.z * inv + bv.z);
    o.w = xv.w + 0.5f * (nv.w * inv + bv.w);
    *(float4*)&out[(size_t)n * 128 + c] = o;
}

// ---------------- GCN: degree + rsqrt ---------------------------------------
__global__ void deg_kernel(const int* __restrict__ dst, int E) {
    int e = blockIdx.x * blockDim.x + threadIdx.x;
    if (e >= E) return;
    atomicAdd(&g_deg[dst[e]], 1.0f);
}
__global__ void dinv_kernel() {
    int n = blockIdx.x * blockDim.x + threadIdx.x;
    if (n >= NB) return;
    g_dinv[n] = rsqrtf(g_deg[n] + 1.0f);
}

// ---------------- GCN edge aggregation: warp per edge ------------------------
__global__ void gcn_agg(const int* __restrict__ src, const int* __restrict__ dst, int E) {
    int gt = blockIdx.x * blockDim.x + threadIdx.x;
    int e = gt >> 5;
    if (e >= E) return;
    int lane = threadIdx.x & 31;
    int s = src[e], d = dst[e];
    float coef = g_dinv[s] * g_dinv[d];
    float4 v = *(const float4*)&g_xwg[(size_t)s * 128 + lane * 4];
    redAddV4(&g_aggB[(size_t)d * 128 + lane * 4],
             coef * v.x, coef * v.y, coef * v.z, coef * v.w);
}

// ---------------- GCN finalize: out = x + 0.2*(agg + xw*dinv^2 + bg) ---------
__global__ void gcn_finalize(const float* __restrict__ x, const float* __restrict__ bg,
                             float* __restrict__ out) {
    int gt = blockIdx.x * blockDim.x + threadIdx.x;
    int n = gt >> 5;
    int lane = threadIdx.x & 31;
    if (n >= NB) return;
    float dv = g_dinv[n];
    float sl = dv * dv;
    int c = lane * 4;
    float4 ag = *(const float4*)&g_aggB[(size_t)n * 128 + c];
    float4 xw = *(const float4*)&g_xwg[(size_t)n * 128 + c];
    float4 xv = *(const float4*)&x[(size_t)n * 128 + c];
    float4 bv = *(const float4*)&bg[c];
    float4 o;
    o.x = xv.x + 0.2f * (ag.x + xw.x * sl + bv.x);
    o.y = xv.y + 0.2f * (ag.y + xw.y * sl + bv.y);
    o.z = xv.z + 0.2f * (ag.z + xw.z * sl + bv.z);
    o.w = xv.w + 0.2f * (ag.w + xw.w * sl + bv.w);
    *(float4*)&out[(size_t)n * 128 + c] = o;
}

// ---------------- launch -----------------------------------------------------
extern "C" void kernel_launch(void* const* d_in, const int* in_sizes, int n_in,
                              void* d_out, int out_size) {
    const float* xb  = (const float*)d_in[0];
    const float* xc  = (const float*)d_in[1];
    const float* xt  = (const float*)d_in[2];
    const float* Ws1 = (const float*)d_in[3];
    const float* Wd1 = (const float*)d_in[4];
    const float* as1 = (const float*)d_in[5];
    const float* ad1 = (const float*)d_in[6];
    const float* b1  = (const float*)d_in[7];
    const float* Ws2 = (const float*)d_in[8];
    const float* Wd2 = (const float*)d_in[9];
    const float* as2 = (const float*)d_in[10];
    const float* ad2 = (const float*)d_in[11];
    const float* b2  = (const float*)d_in[12];
    const float* Wg  = (const float*)d_in[13];
    const float* bg  = (const float*)d_in[14];
    const int* b2c_s = (const int*)d_in[15];
    const int* b2c_d = (const int*)d_in[16];
    const int* c2t_s = (const int*)d_in[17];
    const int* c2t_d = (const int*)d_in[18];
    const int* adj_s = (const int*)d_in[19];
    const int* adj_d = (const int*)d_in[20];

    int Ebc  = in_sizes[15];
    int Ect  = in_sizes[17];
    int Eadj = in_sizes[19];

    float* out   = (float*)d_out;
    float* out_b = out;
    float* out_c = out + (size_t)NB * 128;
    float* out_t = out + (size_t)(NB + NC) * 128;

    const int smem256 = (128 * 256 + 128 * 132) * 4;
    const int smem128 = (128 * 128 + 128 * 132) * 4;
    cudaFuncSetAttribute(gemm_kernel<256>, cudaFuncAttributeMaxDynamicSharedMemorySize, smem256);
    cudaFuncSetAttribute(gemm_kernel<128>, cudaFuncAttributeMaxDynamicSharedMemorySize, smem128);

    float *hs1, *xwg, *hd1, *hs2, *hd2, *num1, *num2;
    float *es1, *ed1, *es2, *ed2, *m1, *s1, *m2, *s2, *e1, *e2;
    cudaGetSymbolAddress((void**)&hs1, g_hs1);
    cudaGetSymbolAddress((void**)&xwg, g_xwg);
    cudaGetSymbolAddress((void**)&hd1, g_hd1);
    cudaGetSymbolAddress((void**)&hs2, g_hs2);
    cudaGetSymbolAddress((void**)&hd2, g_hd2);
    cudaGetSymbolAddress((void**)&num1, g_num1);
    cudaGetSymbolAddress((void**)&num2, g_num2);
    cudaGetSymbolAddress((void**)&es1, g_es1);
    cudaGetSymbolAddress((void**)&ed1, g_ed1);
    cudaGetSymbolAddress((void**)&es2, g_es2);
    cudaGetSymbolAddress((void**)&ed2, g_ed2);
    cudaGetSymbolAddress((void**)&m1, g_m1);
    cudaGetSymbolAddress((void**)&s1, g_s1);
    cudaGetSymbolAddress((void**)&m2, g_m2);
    cudaGetSymbolAddress((void**)&s2, g_s2);
    cudaGetSymbolAddress((void**)&e1, g_e1);
    cudaGetSymbolAddress((void**)&e2, g_e2);

    // 0. init accumulators
    init_kernel<<<2640, 256>>>();

    // 1. building GEMMs (dual: Ws1 and Wg in one pass)
    gemm_kernel<256><<<148, 512, smem256>>>(xb, NB, (NB + 127) / 128, Ws1, Wg, hs1, xwg);
    // 2. cable dst transform for GAT1
    gemm_kernel<128><<<148, 512, smem128>>>(xc, NC, (NC + 127) / 128, Wd1, Wd1, hd1, hd1);

    // 3. attention scalars
    alpha_kernel<<<(NB * 32 + 255) / 256, 256>>>(hs1, as1, es1, NB);
    alpha_kernel<<<(NC * 32 + 255) / 256, 256>>>(hd1, ad1, ed1, NC);

    // 4. GAT1 (building -> cable)
    gat_logit_max<<<(Ebc + 255) / 256, 256>>>(es1, ed1, b2c_s, b2c_d, Ebc, e1, m1);
    gat_accum<<<((size_t)Ebc * 32 + 255) / 256, 256>>>(e1, m1, s1, hs1, b2c_s, b2c_d, num1, Ebc);
    gat_finalize<<<(NC * 32 + 255) / 256, 256>>>(xc, num1, s1, b1, out_c, NC);

    // 5. GAT2 (updated cable -> transformer)
    gemm_kernel<128><<<148, 512, smem128>>>(out_c, NC, (NC + 127) / 128, Ws2, Ws2, hs2, hs2);
    gemm_kernel<128><<<148, 512, smem128>>>(xt, NT, (NT + 127) / 128, Wd2, Wd2, hd2, hd2);
    alpha_kernel<<<(NC * 32 + 255) / 256, 256>>>(hs2, as2, es2, NC);
    alpha_kernel<<<(NT * 32 + 255) / 256, 256>>>(hd2, ad2, ed2, NT);
    gat_logit_max<<<(Ect + 255) / 256, 256>>>(es2, ed2, c2t_s, c2t_d, Ect, e2, m2);
    gat_accum<<<((size_t)Ect * 32 + 255) / 256, 256>>>(e2, m2, s2, hs2, c2t_s, c2t_d, num2, Ect);
    gat_finalize<<<(NT * 32 + 255) / 256, 256>>>(xt, num2, s2, b2, out_t, NT);

    // 6. GCN on building adjacency
    deg_kernel<<<(Eadj + 255) / 256, 256>>>(adj_d, Eadj);
    dinv_kernel<<<(NB + 255) / 256, 256>>>();
    gcn_agg<<<((size_t)Eadj * 32 + 255) / 256, 256>>>(adj_s, adj_d, Eadj);
    gcn_finalize<<<(NB * 32 + 255) / 256, 256>>>(xb, bg, out_b);
}

// round 4
// speedup vs baseline: 1.3209x; 1.3209x over previous
#include <cuda_runtime.h>
#include <cstdint>

#define NB 200000
#define NC 20000
#define NT 2000
#define DD 128
#define EADJ_MAX 1600000

// ---------------- scratch (device globals; no allocation allowed) ------------
__device__ float g_hs1[(size_t)NB * DD];   // x_building @ Ws1
__device__ float g_xwg[(size_t)NB * DD];   // x_building @ Wg
__device__ float g_hd1[(size_t)NC * DD];   // x_cable @ Wd1
__device__ float g_hs2[(size_t)NC * DD];   // h_cable @ Ws2
__device__ float g_num1[(size_t)NC * DD];  // GAT1 numerator
__device__ float g_hd2[(size_t)NT * DD];   // x_transformer @ Wd2
__device__ float g_num2[(size_t)NT * DD];  // GAT2 numerator
__device__ float g_es1[NB * 4];
__device__ float g_ed1[NC * 4];
__device__ float g_es2[NC * 4];
__device__ float g_ed2[NT * 4];
__device__ float g_m1[NC * 4];
__device__ float g_s1[NC * 4];
__device__ float g_m2[NT * 4];
__device__ float g_s2[NT * 4];
__device__ float g_e1[200000 * 4];
__device__ float g_e2[20000 * 4];
__device__ float g_dinv[NB];
__device__ int   g_degi[NB];
__device__ int   g_off[NB + 1];
__device__ int   g_cursor[NB];
__device__ int   g_csrc[EADJ_MAX];
__device__ int   g_bsum[512];

// ---------------- helpers ----------------------------------------------------
__device__ __forceinline__ unsigned long long f2ull(float x, float y) {
    unsigned long long r;
    asm("mov.b64 %0, {%1,%2};" : "=l"(r) : "f"(x), "f"(y));
    return r;
}
__device__ __forceinline__ float2 ull2f2(unsigned long long v) {
    float2 r;
    asm("mov.b64 {%0,%1}, %2;" : "=f"(r.x), "=f"(r.y) : "l"(v));
    return r;
}
#define FMA2(acc, a, b) asm("fma.rn.f32x2 %0, %1, %2, %0;" : "+l"(acc) : "l"(a), "l"(b))

__device__ __forceinline__ void redAddV4(float* p, float a, float b, float c, float d) {
    asm volatile("red.global.add.v4.f32 [%0], {%1,%2,%3,%4};"
                 :: "l"(p), "f"(a), "f"(b), "f"(c), "f"(d) : "memory");
}

__device__ __forceinline__ void atomicMaxFloat(float* addr, float v) {
    if (v >= 0.0f) atomicMax((int*)addr, __float_as_int(v));
    else atomicMin((unsigned int*)addr, (unsigned int)__float_as_int(v));
}

// ---------------- init --------------------------------------------------------
__global__ void init_kernel() {
    int idx = blockIdx.x * blockDim.x + threadIdx.x;
    int stride = gridDim.x * blockDim.x;
    float4 z = make_float4(0.f, 0.f, 0.f, 0.f);
    for (int i = idx; i < NC * DD / 4; i += stride) ((float4*)g_num1)[i] = z;
    for (int i = idx; i < NT * DD / 4; i += stride) ((float4*)g_num2)[i] = z;
    for (int i = idx; i < NB; i += stride) { g_degi[i] = 0; g_cursor[i] = 0; }
    for (int i = idx; i < NC * 4; i += stride) { g_s1[i] = 0.f; g_m1[i] = -1e30f; }
    for (int i = idx; i < NT * 4; i += stride) { g_s2[i] = 0.f; g_m2[i] = -1e30f; }
}

// ---------------- fp32 GEMM, W SMEM-resident, FFMA2, fused alpha dot ----------
// O[row, col] = sum_k X[row,k] * W[k,col], K = 128, NCOLS = 128 or 256.
// If aout != null: aout[row*4 + h] = sum_c O0[row, h*32 + c] * avec[h*32 + c]
// (alpha dot applies to columns < 128, i.e. O0).
template <int NCOLS>
__global__ void __launch_bounds__(512, 1)
gemm_kernel(const float* __restrict__ X, int M, int ntiles,
            const float* __restrict__ W0, const float* __restrict__ W1,
            float* __restrict__ O0, float* __restrict__ O1,
            const float* __restrict__ avec, float* __restrict__ aout) {
    extern __shared__ float smem[];
    float* sW = smem;                          // 128 * NCOLS
    float* sX = smem + 128 * NCOLS;            // 128 rows * 132 (padded)
    float* aS = smem + 128 * NCOLS + 128 * 132; // 128 alpha coefficients
    const int tid = threadIdx.x;

    for (int i = tid; i < 128 * NCOLS / 4; i += 512) {
        int k = (i * 4) / NCOLS;
        int n = (i * 4) % NCOLS;
        const float* src = (n < 128) ? &W0[k * 128 + n] : &W1[k * 128 + (n - 128)];
        *(float4*)&sW[i * 4] = *(const float4*)src;
    }
    if (aout && tid < 128) aS[tid] = avec[tid];

    const int tx = tid & 15;
    const int ty = tid >> 4;
    const int lane = tid & 31;
    constexpr int NCH = NCOLS / 64;

    for (int tile = blockIdx.x; tile < ntiles; tile += gridDim.x) {
        int row0 = tile * 128;
        __syncthreads();
        for (int i = tid; i < 128 * 32; i += 512) {
            int r = i >> 5;
            int c4 = (i & 31) * 4;
            float4 v = make_float4(0.f, 0.f, 0.f, 0.f);
            if (row0 + r < M) v = *(const float4*)&X[(size_t)(row0 + r) * 128 + c4];
            *(float4*)&sX[r * 132 + c4] = v;
        }
        __syncthreads();

        unsigned long long acc[4][NCH][2];
        #pragma unroll
        for (int i = 0; i < 4; i++)
            #pragma unroll
            for (int c = 0; c < NCH; c++) { acc[i][c][0] = 0ull; acc[i][c][1] = 0ull; }

        #pragma unroll 4
        for (int k = 0; k < 128; k++) {
            unsigned long long a2[4];
            #pragma unroll
            for (int i = 0; i < 4; i++) {
                float av = sX[(ty * 4 + i) * 132 + k];
                a2[i] = f2ull(av, av);
            }
            #pragma unroll
            for (int c = 0; c < NCH; c++) {
                ulonglong2 b = *(const ulonglong2*)&sW[k * NCOLS + c * 64 + tx * 4];
                #pragma unroll
                for (int i = 0; i < 4; i++) {
                    FMA2(acc[i][c][0], a2[i], b.x);
                    FMA2(acc[i][c][1], a2[i], b.y);
                }
            }
        }

        #pragma unroll
        for (int i = 0; i < 4; i++) {
            int row = row0 + ty * 4 + i;
            float4 vv[NCH];
            #pragma unroll
            for (int c = 0; c < NCH; c++) {
                float2 lo = ull2f2(acc[i][c][0]);
                float2 hi = ull2f2(acc[i][c][1]);
                vv[c] = make_float4(lo.x, lo.y, hi.x, hi.y);
            }
            // fused alpha partial dots (cols < 128): chunk0 -> head tx>>3,
            // chunk1 -> head 2+(tx>>3). Reduce over the 8 lanes sharing a head.
            if (aout) {
                int c0 = tx * 4;
                float pA = vv[0].x * aS[c0] + vv[0].y * aS[c0 + 1]
                         + vv[0].z * aS[c0 + 2] + vv[0].w * aS[c0 + 3];
                float pB = vv[1].x * aS[64 + c0] + vv[1].y * aS[64 + c0 + 1]
                         + vv[1].z * aS[64 + c0 + 2] + vv[1].w * aS[64 + c0 + 3];
                #pragma unroll
                for (int msk = 1; msk < 8; msk <<= 1) {
                    pA += __shfl_xor_sync(0xffffffffu, pA, msk);
                    pB += __shfl_xor_sync(0xffffffffu, pB, msk);
                }
                if (row < M && (lane & 7) == 0) {
                    int hb = (lane >> 3) & 1;
                    aout[(size_t)row * 4 + hb] = pA;
                    aout[(size_t)row * 4 + 2 + hb] = pB;
                }
            }
            if (row < M) {
                #pragma unroll
                for (int c = 0; c < NCH; c++) {
                    int col = c * 64 + tx * 4;
                    if (col < 128) *(float4*)&O0[(size_t)row * 128 + col] = vv[c];
                    else           *(float4*)&O1[(size_t)row * 128 + col - 128] = vv[c];
                }
            }
        }
    }
}

// ---------------- GAT pass A: logits + segment max ---------------------------
__global__ void gat_logit_max(const float* __restrict__ es, const float* __restrict__ ed,
                              const int* __restrict__ src, const int* __restrict__ dst,
                              int E, float* __restrict__ elog, float* __restrict__ m) {
    int e = blockIdx.x * blockDim.x + threadIdx.x;
    if (e >= E) return;
    int s = src[e], d = dst[e];
    float4 a = *(const float4*)&es[s * 4];
    float4 b = *(const float4*)&ed[d * 4];
    float4 v; float t;
    t = a.x + b.x; v.x = t > 0.f ? t : 0.2f * t;
    t = a.y + b.y; v.y = t > 0.f ? t : 0.2f * t;
    t = a.z + b.z; v.z = t > 0.f ? t : 0.2f * t;
    t = a.w + b.w; v.w = t > 0.f ? t : 0.2f * t;
    *(float4*)&elog[e * 4] = v;
    atomicMaxFloat(&m[d * 4 + 0], v.x);
    atomicMaxFloat(&m[d * 4 + 1], v.y);
    atomicMaxFloat(&m[d * 4 + 2], v.z);
    atomicMaxFloat(&m[d * 4 + 3], v.w);
}

// ---------------- GAT pass B: exp, segment sum, weighted numerator -----------
__global__ void gat_accum(const float* __restrict__ elog, const float* __restrict__ m,
                          float* __restrict__ ssum, const float* __restrict__ hs,
                          const int* __restrict__ src, const int* __restrict__ dst,
                          float* __restrict__ num, int E) {
    int gt = blockIdx.x * blockDim.x + threadIdx.x;
    int e = gt >> 5;
    if (e >= E) return;
    int lane = threadIdx.x & 31;
    int s = src[e], d = dst[e];
    int h = lane >> 3;
    float wv = __expf(elog[e * 4 + h] - m[d * 4 + h]);
    if ((lane & 7) == 0) atomicAdd(&ssum[d * 4 + h], wv);
    float4 hv = *(const float4*)&hs[(size_t)s * 128 + lane * 4];
    redAddV4(&num[(size_t)d * 128 + lane * 4], wv * hv.x, wv * hv.y, wv * hv.z, wv * hv.w);
}

// ---------------- GAT finalize -----------------------------------------------
__global__ void gat_finalize(const float* __restrict__ x, const float* __restrict__ num,
                             const float* __restrict__ ssum, const float* __restrict__ bias,
                             float* __restrict__ out, int N) {
    int gt = blockIdx.x * blockDim.x + threadIdx.x;
    int n = gt >> 5;
    int lane = threadIdx.x & 31;
    if (n >= N) return;
    int h = lane >> 3;
    float inv = 1.0f / (ssum[n * 4 + h] + 1e-16f);
    int c = lane * 4;
    float4 nv = *(const float4*)&num[(size_t)n * 128 + c];
    float4 xv = *(const float4*)&x[(size_t)n * 128 + c];
    float4 bv = *(const float4*)&bias[c];
    float4 o;
    o.x = xv.x + 0.5f * (nv.x * inv + bv.x);
    o.y = xv.y + 0.5f * (nv.y * inv + bv.y);
    o.z = xv.z + 0.5f * (nv.z * inv + bv.z);
    o.w = xv.w + 0.5f * (nv.w * inv + bv.w);
    *(float4*)&out[(size_t)n * 128 + c] = o;
}

// ---------------- GCN CSR build ----------------------------------------------
__global__ void deg_int(const int* __restrict__ dst, int E) {
    int e = blockIdx.x * blockDim.x + threadIdx.x;
    if (e < E) atomicAdd(&g_degi[dst[e]], 1);
}
__global__ void scan1() {
    __shared__ int sh[512];
    int b = blockIdx.x, t = threadIdx.x;
    int i = b * 512 + t;
    sh[t] = (i < NB) ? g_degi[i] : 0;
    __syncthreads();
    for (int s = 256; s > 0; s >>= 1) {
        if (t < s) sh[t] += sh[t + s];
        __syncthreads();
    }
    if (t == 0) g_bsum[b] = sh[0];
}
__global__ void scan2(int nblk) {
    __shared__ int sh[512];
    int t = threadIdx.x;
    sh[t] = (t < nblk) ? g_bsum[t] : 0;
    __syncthreads();
    if (t == 0) {
        int run = 0;
        for (int i = 0; i < nblk; i++) { int x = sh[i]; sh[i] = run; run += x; }
        g_off[NB] = run;
    }
    __syncthreads();
    if (t < nblk) g_bsum[t] = sh[t];
}
__global__ void scan3() {
    __shared__ int sh[512];
    int b = blockIdx.x, t = threadIdx.x;
    int i = b * 512 + t;
    int v = (i < NB) ? g_degi[i] : 0;
    sh[t] = v;
    __syncthreads();
    int x = v;
    for (int d = 1; d < 512; d <<= 1) {
        int y = (t >= d) ? sh[t - d] : 0;
        __syncthreads();
        x += y;
        sh[t] = x;
        __syncthreads();
    }
    if (i < NB) g_off[i] = g_bsum[b] + x - v;
}
__global__ void dinv_kernel() {
    int n = blockIdx.x * blockDim.x + threadIdx.x;
    if (n < NB) g_dinv[n] = rsqrtf((float)g_degi[n] + 1.0f);
}
__global__ void csr_fill(const int* __restrict__ src, const int* __restrict__ dst, int E) {
    int e = blockIdx.x * blockDim.x + threadIdx.x;
    if (e >= E) return;
    int d = dst[e];
    int slot = g_off[d] + atomicAdd(&g_cursor[d], 1);
    g_csrc[slot] = src[e];
}

// ---------------- GCN: warp per dst, register accumulate, fused epilogue -----
__global__ void __launch_bounds__(256, 8)
gcn_csr(const float* __restrict__ xb, const float* __restrict__ bg,
        float* __restrict__ out) {
    int d = blockIdx.x * 8 + (threadIdx.x >> 5);
    if (d >= NB) return;
    int lane = threadIdx.x & 31;
    int start = g_off[d], end = g_off[d + 1];
    float dv = g_dinv[d];
    float4 acc = make_float4(0.f, 0.f, 0.f, 0.f);
    for (int i = start; i < end; i++) {
        int s = g_csrc[i];
        float coef = g_dinv[s] * dv;
        float4 v = *(const float4*)&g_xwg[(size_t)s * 128 + lane * 4];
        acc.x += coef * v.x; acc.y += coef * v.y;
        acc.z += coef * v.z; acc.w += coef * v.w;
    }
    float sl = dv * dv;
    int c = lane * 4;
    float4 xw = *(const float4*)&g_xwg[(size_t)d * 128 + c];
    float4 xv = *(const float4*)&xb[(size_t)d * 128 + c];
    float4 bv = *(const float4*)&bg[c];
    float4 o;
    o.x = xv.x + 0.2f * (acc.x + xw.x * sl + bv.x);
    o.y = xv.y + 0.2f * (acc.y + xw.y * sl + bv.y);
    o.z = xv.z + 0.2f * (acc.z + xw.z * sl + bv.z);
    o.w = xv.w + 0.2f * (acc.w + xw.w * sl + bv.w);
    *(float4*)&out[(size_t)d * 128 + c] = o;
}

// ---------------- launch -----------------------------------------------------
extern "C" void kernel_launch(void* const* d_in, const int* in_sizes, int n_in,
                              void* d_out, int out_size) {
    const float* xb  = (const float*)d_in[0];
    const float* xc  = (const float*)d_in[1];
    const float* xt  = (const float*)d_in[2];
    const float* Ws1 = (const float*)d_in[3];
    const float* Wd1 = (const float*)d_in[4];
    const float* as1 = (const float*)d_in[5];
    const float* ad1 = (const float*)d_in[6];
    const float* b1  = (const float*)d_in[7];
    const float* Ws2 = (const float*)d_in[8];
    const float* Wd2 = (const float*)d_in[9];
    const float* as2 = (const float*)d_in[10];
    const float* ad2 = (const float*)d_in[11];
    const float* b2  = (const float*)d_in[12];
    const float* Wg  = (const float*)d_in[13];
    const float* bg  = (const float*)d_in[14];
    const int* b2c_s = (const int*)d_in[15];
    const int* b2c_d = (const int*)d_in[16];
    const int* c2t_s = (const int*)d_in[17];
    const int* c2t_d = (const int*)d_in[18];
    const int* adj_s = (const int*)d_in[19];
    const int* adj_d = (const int*)d_in[20];

    int Ebc  = in_sizes[15];
    int Ect  = in_sizes[17];
    int Eadj = in_sizes[19];

    float* out   = (float*)d_out;
    float* out_b = out;
    float* out_c = out + (size_t)NB * 128;
    float* out_t = out + (size_t)(NB + NC) * 128;

    const int smem256 = (128 * 256 + 128 * 132 + 128) * 4;
    const int smem128 = (128 * 128 + 128 * 132 + 128) * 4;
    cudaFuncSetAttribute(gemm_kernel<256>, cudaFuncAttributeMaxDynamicSharedMemorySize, smem256);
    cudaFuncSetAttribute(gemm_kernel<128>, cudaFuncAttributeMaxDynamicSharedMemorySize, smem128);

    float *hs1, *xwg, *hd1, *hs2, *hd2, *num1, *num2;
    float *es1, *ed1, *es2, *ed2, *m1, *s1, *m2, *s2, *e1, *e2;
    cudaGetSymbolAddress((void**)&hs1, g_hs1);
    cudaGetSymbolAddress((void**)&xwg, g_xwg);
    cudaGetSymbolAddress((void**)&hd1, g_hd1);
    cudaGetSymbolAddress((void**)&hs2, g_hs2);
    cudaGetSymbolAddress((void**)&hd2, g_hd2);
    cudaGetSymbolAddress((void**)&num1, g_num1);
    cudaGetSymbolAddress((void**)&num2, g_num2);
    cudaGetSymbolAddress((void**)&es1, g_es1);
    cudaGetSymbolAddress((void**)&ed1, g_ed1);
    cudaGetSymbolAddress((void**)&es2, g_es2);
    cudaGetSymbolAddress((void**)&ed2, g_ed2);
    cudaGetSymbolAddress((void**)&m1, g_m1);
    cudaGetSymbolAddress((void**)&s1, g_s1);
    cudaGetSymbolAddress((void**)&m2, g_m2);
    cudaGetSymbolAddress((void**)&s2, g_s2);
    cudaGetSymbolAddress((void**)&e1, g_e1);
    cudaGetSymbolAddress((void**)&e2, g_e2);

    int nblk = (NB + 511) / 512;

    // init + CSR build (independent of GEMMs)
    init_kernel<<<2048, 256>>>();
    deg_int<<<(Eadj + 255) / 256, 256>>>(adj_d, Eadj);
    scan1<<<nblk, 512>>>();
    scan2<<<1, 512>>>(nblk);
    scan3<<<nblk, 512>>>();
    dinv_kernel<<<(NB + 255) / 256, 256>>>();
    csr_fill<<<(Eadj + 255) / 256, 256>>>(adj_s, adj_d, Eadj);

    // 1. building dual GEMM (Ws1 | Wg) with fused es1
    gemm_kernel<256><<<148, 512, smem256>>>(xb, NB, (NB + 127) / 128, Ws1, Wg,
                                            hs1, xwg, as1, es1);
    // 2. cable dst transform with fused ed1
    gemm_kernel<128><<<148, 512, smem128>>>(xc, NC, (NC + 127) / 128, Wd1, Wd1,
                                            hd1, hd1, ad1, ed1);

    // 3. GAT1 (building -> cable)
    gat_logit_max<<<(Ebc + 255) / 256, 256>>>(es1, ed1, b2c_s, b2c_d, Ebc, e1, m1);
    gat_accum<<<(int)(((size_t)Ebc * 32 + 255) / 256), 256>>>(e1, m1, s1, hs1, b2c_s, b2c_d, num1, Ebc);
    gat_finalize<<<(NC * 32 + 255) / 256, 256>>>(xc, num1, s1, b1, out_c, NC);

    // 4. GAT2 (updated cable -> transformer)
    gemm_kernel<128><<<148, 512, smem128>>>(out_c, NC, (NC + 127) / 128, Ws2, Ws2,
                                            hs2, hs2, as2, es2);
    gemm_kernel<128><<<16, 512, smem128>>>(xt, NT, (NT + 127) / 128, Wd2, Wd2,
                                           hd2, hd2, ad2, ed2);
    gat_logit_max<<<(Ect + 255) / 256, 256>>>(es2, ed2, c2t_s, c2t_d, Ect, e2, m2);
    gat_accum<<<(int)(((size_t)Ect * 32 + 255) / 256), 256>>>(e2, m2, s2, hs2, c2t_s, c2t_d, num2, Ect);
    gat_finalize<<<(NT * 32 + 255) / 256, 256>>>(xt, num2, s2, b2, out_t, NT);

    // 5. GCN building (CSR, fused finalize)
    gcn_csr<<<(NB + 7) / 8, 256>>>(xb, bg, out_b);
}